// round 2
// baseline (speedup 1.0000x reference)
#include <cuda_runtime.h>
#include <cuda_bf16.h>
#include <cstdint>

// Problem constants (match reference_code)
#define NN 100000
#define EE 1250000
#define F  64

// Scratch (no allocations allowed -> device globals)
__device__ float g_h[NN * F];      // h1, then h2 (overwritten)
__device__ float g_agg1[NN * F];   // layer-1 aggregation / z1 source
__device__ float g_agg2[NN * F];   // layer-2 aggregation
__device__ float g_dinv[NN];
__device__ int   g_deg[NN];
__device__ float g_colsum[F];

// ---------------------------------------------------------------------------
// 0) init: deg=1 (self loop), colsum=0   (must run every call: atomics accumulate)
__global__ void k_init() {
    int i = blockIdx.x * blockDim.x + threadIdx.x;
    if (i < NN) g_deg[i] = 1;
    if (i < F) g_colsum[i] = 0.0f;
}

// 1) degree histogram over dst
__global__ void k_deg(const int* __restrict__ dst) {
    int i = blockIdx.x * blockDim.x + threadIdx.x;
    if (i < EE) atomicAdd(&g_deg[dst[i]], 1);
}

// 2) dinv = rsqrt(deg)
__global__ void k_dinv() {
    int i = blockIdx.x * blockDim.x + threadIdx.x;
    if (i < NN) g_dinv[i] = rsqrtf((float)g_deg[i]);
}

// 3) h1 = x @ W1 ; agg1 = h1 * dinv^2  (self-loop contribution)
//    block = 256 threads = 4 nodes x 64 cols
__global__ void __launch_bounds__(256) k_gemm1(const float* __restrict__ x,
                                               const float* __restrict__ W1) {
    __shared__ float sW[8 * F];
    __shared__ float sx[4][8];
    int tid = threadIdx.x;
    for (int i = tid; i < 8 * F; i += 256) sW[i] = W1[i];
    int node0 = blockIdx.x * 4;
    if (tid < 32) {
        int nn = node0 + (tid >> 3);
        if (nn < NN) sx[tid >> 3][tid & 7] = x[nn * 8 + (tid & 7)];
    }
    __syncthreads();
    int ln = tid >> 6, col = tid & 63;
    int node = node0 + ln;
    if (node < NN) {
        float acc = 0.0f;
#pragma unroll
        for (int k = 0; k < 8; k++) acc += sx[ln][k] * sW[k * F + col];
        float di = g_dinv[node];
        g_h[node * F + col] = acc;
        g_agg1[node * F + col] = acc * di * di;
    }
}

// 4) scatter: agg[dst] += h[src] * dinv[src]*dinv[dst]
//    half-warp (16 lanes) per edge; each lane: 1 float4 gather + 1 red.v4
__global__ void __launch_bounds__(256) k_scatter(const int* __restrict__ src,
                                                 const int* __restrict__ dst,
                                                 const float* __restrict__ h,
                                                 float* __restrict__ agg) {
    int e = blockIdx.x * 16 + (threadIdx.x >> 4);
    if (e >= EE) return;
    int lane = threadIdx.x & 15;
    int s = __ldg(src + e);
    int d = __ldg(dst + e);
    float w = __ldg(&g_dinv[s]) * __ldg(&g_dinv[d]);
    float4 v = *(reinterpret_cast<const float4*>(h + (size_t)s * F) + lane);
    float* p = agg + (size_t)d * F + lane * 4;
    asm volatile("red.global.add.v4.f32 [%0], {%1,%2,%3,%4};"
                 :: "l"(p), "f"(v.x * w), "f"(v.y * w), "f"(v.z * w), "f"(v.w * w)
                 : "memory");
}

// 5) z1 = relu(agg1 + b1); h2 = z1 @ W2; agg2 = h2 * dinv^2
//    block = 256 threads = 4 nodes x 64 cols; W2 staged in smem (16KB)
__global__ void __launch_bounds__(256) k_gemm2(const float* __restrict__ W2,
                                               const float* __restrict__ b1) {
    __shared__ float sW[F * F];
    __shared__ float sz[4][F];
    int tid = threadIdx.x;
    for (int i = tid; i < F * F; i += 256) sW[i] = W2[i];
    int node0 = blockIdx.x * 4;
    int ln = tid >> 6, col = tid & 63;
    int node = node0 + ln;
    if (node < NN) sz[ln][col] = fmaxf(g_agg1[node * F + col] + b1[col], 0.0f);
    __syncthreads();
    if (node < NN) {
        float acc = 0.0f;
#pragma unroll
        for (int k = 0; k < F; k++) acc += sz[ln][k] * sW[k * F + col];
        float di = g_dinv[node];
        g_h[node * F + col] = acc;          // h2 (h1 dead)
        g_agg2[node * F + col] = acc * di * di;
    }
}

// 6) column sums of agg2 (mean pool numerator)
__global__ void __launch_bounds__(256) k_colsum() {
    int tid = threadIdx.x;
    int col = tid & 63, grp = tid >> 6;
    float acc = 0.0f;
    for (int n = blockIdx.x * 4 + grp; n < NN; n += gridDim.x * 4)
        acc += g_agg2[(size_t)n * F + col];
    __shared__ float sred[4][F];
    sred[grp][col] = acc;
    __syncthreads();
    if (grp == 0) {
        float v = sred[0][col] + sred[1][col] + sred[2][col] + sred[3][col];
        atomicAdd(&g_colsum[col], v);
    }
}

// 7) head: g = colsum/N + b2 ; s = relu(state@Wm + bm) ; out = [g,s]@Wc + bc
//    launch with 64 threads (2 warps)
__global__ void k_final(const float* __restrict__ state, const float* __restrict__ Wm,
                        const float* __restrict__ bm, const float* __restrict__ b2,
                        const float* __restrict__ Wc, const float* __restrict__ bc,
                        float* __restrict__ out) {
    int c = threadIdx.x;  // 0..63
    float sv = bm[c];
#pragma unroll
    for (int k = 0; k < 8; k++) sv += state[k] * Wm[k * F + c];
    sv = fmaxf(sv, 0.0f);
    float gv = g_colsum[c] * (1.0f / (float)NN) + b2[c];
    float p0 = gv * Wc[c * 2 + 0] + sv * Wc[(F + c) * 2 + 0];
    float p1 = gv * Wc[c * 2 + 1] + sv * Wc[(F + c) * 2 + 1];
#pragma unroll
    for (int o = 16; o > 0; o >>= 1) {
        p0 += __shfl_down_sync(0xffffffffu, p0, o);
        p1 += __shfl_down_sync(0xffffffffu, p1, o);
    }
    __shared__ float s0[2], s1[2];
    if ((c & 31) == 0) { s0[c >> 5] = p0; s1[c >> 5] = p1; }
    __syncthreads();
    if (c == 0) {
        out[0] = s0[0] + s0[1] + bc[0];
        out[1] = s1[0] + s1[1] + bc[1];
    }
}

// ---------------------------------------------------------------------------
extern "C" void kernel_launch(void* const* d_in, const int* in_sizes, int n_in,
                              void* d_out, int out_size) {
    // metadata order: x, state, W1, b1, W2, b2, Wm, bm, Wc, bc, edge_index
    const float* x     = (const float*)d_in[0];
    const float* state = (const float*)d_in[1];
    const float* W1    = (const float*)d_in[2];
    const float* b1    = (const float*)d_in[3];
    const float* W2    = (const float*)d_in[4];
    const float* b2    = (const float*)d_in[5];
    const float* Wm    = (const float*)d_in[6];
    const float* bm    = (const float*)d_in[7];
    const float* Wc    = (const float*)d_in[8];
    const float* bc    = (const float*)d_in[9];
    const int*   ei    = (const int*)d_in[10];
    const int* src = ei;
    const int* dst = ei + EE;
    float* out = (float*)d_out;

    float* d_h    = nullptr; cudaGetSymbolAddress((void**)&d_h,    g_h);
    float* d_agg1 = nullptr; cudaGetSymbolAddress((void**)&d_agg1, g_agg1);
    float* d_agg2 = nullptr; cudaGetSymbolAddress((void**)&d_agg2, g_agg2);

    k_init<<<(NN + 255) / 256, 256>>>();
    k_deg<<<(EE + 255) / 256, 256>>>(dst);
    k_dinv<<<(NN + 255) / 256, 256>>>();
    k_gemm1<<<(NN + 3) / 4, 256>>>(x, W1);
    k_scatter<<<(EE + 15) / 16, 256>>>(src, dst, d_h, d_agg1);
    k_gemm2<<<(NN + 3) / 4, 256>>>(W2, b1);
    k_scatter<<<(EE + 15) / 16, 256>>>(src, dst, d_h, d_agg2);
    k_colsum<<<512, 256>>>();
    k_final<<<1, 64>>>(state, Wm, bm, b2, Wc, bc, out);
}

// round 8
// speedup vs baseline: 3.9168x; 3.9168x over previous
#include <cuda_runtime.h>
#include <cuda_bf16.h>
#include <cstdint>

#define NN 100000
#define EE 1250000
#define F  64

// Scratch (device globals; no allocation allowed)
__device__ float g_h[NN * F];      // h1
__device__ float g_agg1[NN * F];   // layer-1 aggregation
__device__ float g_dinv[NN];
__device__ float g_S[NN];          // S[n] = sum_{e:src=n} dinv[dst_e]
__device__ int   g_deg[NN];
__device__ float g_u[F];           // u[k] = sum_n coef[n] * z1[n,k]

// ---------------------------------------------------------------------------
// 0) reset accumulators (must run every call)
__global__ void k_init() {
    int i = blockIdx.x * blockDim.x + threadIdx.x;
    if (i < NN) { g_deg[i] = 1; g_S[i] = 0.0f; }
    if (i < F) g_u[i] = 0.0f;
}

// 1) degree histogram over dst (self-loop pre-counted as 1)
__global__ void k_deg(const int* __restrict__ dst) {
    int i = blockIdx.x * blockDim.x + threadIdx.x;
    if (i < EE) atomicAdd(&g_deg[dst[i]], 1);
}

// 2) dinv = rsqrt(deg)
__global__ void k_dinv() {
    int i = blockIdx.x * blockDim.x + threadIdx.x;
    if (i < NN) g_dinv[i] = rsqrtf((float)g_deg[i]);
}

// 3) h1 = x @ W1 ; agg1 = h1 * dinv^2 (self-loop term)
//    block = 256 threads = 16 nodes x 16 threads (4 cols each); grid = NN/16
__global__ void __launch_bounds__(256) k_gemm1(const float* __restrict__ x,
                                               const float* __restrict__ W1) {
    __shared__ float sW[8][F];
    __shared__ float sx[16][8];
    int tid = threadIdx.x;
    // FIX: 8*F = 512 entries, 256 threads -> must loop (was the rel_err 3e-2 bug)
    for (int i = tid; i < 8 * F; i += 256) sW[i >> 6][i & 63] = W1[i];
    int node0 = blockIdx.x * 16;
    if (tid < 128) sx[tid >> 3][tid & 7] = x[node0 * 8 + tid];
    __syncthreads();
    int ln = tid >> 4;                // node within block
    int c0 = (tid & 15) * 4;          // first of 4 cols
    int node = node0 + ln;
    float a0 = 0.f, a1 = 0.f, a2 = 0.f, a3 = 0.f;
#pragma unroll
    for (int k = 0; k < 8; k++) {
        float xv = sx[ln][k];
        a0 += xv * sW[k][c0 + 0];
        a1 += xv * sW[k][c0 + 1];
        a2 += xv * sW[k][c0 + 2];
        a3 += xv * sW[k][c0 + 3];
    }
    float di = g_dinv[node];
    float w = di * di;
    size_t base = (size_t)node * F + c0;
    *reinterpret_cast<float4*>(g_h + base)    = make_float4(a0, a1, a2, a3);
    *reinterpret_cast<float4*>(g_agg1 + base) = make_float4(a0 * w, a1 * w, a2 * w, a3 * w);
}

// 4) layer-1 scatter: agg1[dst] += h1[src]*dinv[s]*dinv[d]
//    + fused: S[src] += dinv[dst]   (layer-2 algebraic elimination)
//    half-warp (16 lanes) per edge: 1 float4 gather + 1 red.v4 per lane
__global__ void __launch_bounds__(256) k_scatter(const int* __restrict__ src,
                                                 const int* __restrict__ dst) {
    int e = blockIdx.x * 16 + (threadIdx.x >> 4);
    if (e >= EE) return;
    int lane = threadIdx.x & 15;
    int s = __ldg(src + e);
    int d = __ldg(dst + e);
    float ds = __ldg(&g_dinv[s]);
    float dd = __ldg(&g_dinv[d]);
    float w = ds * dd;
    float4 v = *(reinterpret_cast<const float4*>(g_h + (size_t)s * F) + lane);
    float* p = g_agg1 + (size_t)d * F + lane * 4;
    asm volatile("red.global.add.v4.f32 [%0], {%1,%2,%3,%4};"
                 :: "l"(p), "f"(v.x * w), "f"(v.y * w), "f"(v.z * w), "f"(v.w * w)
                 : "memory");
    if (lane == 0) atomicAdd(&g_S[s], dd);
}

// 5) u[k] = sum_n coef[n] * relu(agg1[n,k] + b1[k]),
//    coef[n] = dinv[n]*(S[n] + dinv[n])
//    Identity: mean-pool(GCNconv2 pre-bias) = (u @ W2)/N, so layer-2's
//    scatter + GEMM + colsum all collapse into this pass + a 64x64 dot.
__global__ void __launch_bounds__(256) k_u(const float* __restrict__ b1) {
    int tid = threadIdx.x;
    int col = tid & 63, grp = tid >> 6;
    float bb = b1[col];
    float acc = 0.0f;
    for (int n = blockIdx.x * 4 + grp; n < NN; n += gridDim.x * 4) {
        float di = g_dinv[n];
        float coef = di * (g_S[n] + di);
        acc += coef * fmaxf(g_agg1[(size_t)n * F + col] + bb, 0.0f);
    }
    __shared__ float sred[4][F];
    sred[grp][col] = acc;
    __syncthreads();
    if (grp == 0) {
        float v = sred[0][col] + sred[1][col] + sred[2][col] + sred[3][col];
        atomicAdd(&g_u[col], v);
    }
}

// 6) head: g = (u @ W2)/N + b2 ; s = relu(state@Wm + bm) ; out = [g,s]@Wc + bc
__global__ void k_final(const float* __restrict__ state, const float* __restrict__ Wm,
                        const float* __restrict__ bm, const float* __restrict__ W2,
                        const float* __restrict__ b2, const float* __restrict__ Wc,
                        const float* __restrict__ bc, float* __restrict__ out) {
    int c = threadIdx.x;  // 0..63
    float gv = 0.0f;
#pragma unroll 8
    for (int k = 0; k < F; k++) gv += g_u[k] * W2[k * F + c];
    gv = gv * (1.0f / (float)NN) + b2[c];
    float sv = bm[c];
#pragma unroll
    for (int k = 0; k < 8; k++) sv += state[k] * Wm[k * F + c];
    sv = fmaxf(sv, 0.0f);
    float p0 = gv * Wc[c * 2 + 0] + sv * Wc[(F + c) * 2 + 0];
    float p1 = gv * Wc[c * 2 + 1] + sv * Wc[(F + c) * 2 + 1];
#pragma unroll
    for (int o = 16; o > 0; o >>= 1) {
        p0 += __shfl_down_sync(0xffffffffu, p0, o);
        p1 += __shfl_down_sync(0xffffffffu, p1, o);
    }
    __shared__ float s0[2], s1[2];
    if ((c & 31) == 0) { s0[c >> 5] = p0; s1[c >> 5] = p1; }
    __syncthreads();
    if (c == 0) {
        out[0] = s0[0] + s0[1] + bc[0];
        out[1] = s1[0] + s1[1] + bc[1];
    }
}

// ---------------------------------------------------------------------------
extern "C" void kernel_launch(void* const* d_in, const int* in_sizes, int n_in,
                              void* d_out, int out_size) {
    // metadata order: x, state, W1, b1, W2, b2, Wm, bm, Wc, bc, edge_index
    const float* x     = (const float*)d_in[0];
    const float* state = (const float*)d_in[1];
    const float* W1    = (const float*)d_in[2];
    const float* b1    = (const float*)d_in[3];
    const float* W2    = (const float*)d_in[4];
    const float* b2    = (const float*)d_in[5];
    const float* Wm    = (const float*)d_in[6];
    const float* bm    = (const float*)d_in[7];
    const float* Wc    = (const float*)d_in[8];
    const float* bc    = (const float*)d_in[9];
    const int*   ei    = (const int*)d_in[10];
    const int* src = ei;
    const int* dst = ei + EE;
    float* out = (float*)d_out;

    k_init<<<(NN + 255) / 256, 256>>>();
    k_deg<<<(EE + 255) / 256, 256>>>(dst);
    k_dinv<<<(NN + 255) / 256, 256>>>();
    k_gemm1<<<NN / 16, 256>>>(x, W1);                 // 100000 % 16 == 0
    k_scatter<<<(EE + 15) / 16, 256>>>(src, dst);
    k_u<<<512, 256>>>(b1);
    k_final<<<1, 64>>>(state, Wm, bm, W2, b2, Wc, bc, out);
}